// round 13
// baseline (speedup 1.0000x reference)
#include <cuda_runtime.h>
#include <cuda_fp16.h>
#include <cstdint>

// Problem constants
#define Bn 131072
#define Cn 128
#define En 128
#define NPERS 296            // persistent CTAs (2 per SM on 148 SMs)
#define NW_TOT (NPERS * 8)   // 2368 warps
#define NITEMS (Bn / 16)     // 8192 work items, 16 rows each

// ArcFace constants (m = 1.0, s = 100)
#define COSM 0.5403023058681398f
#define SINM 0.8414709848078965f
#define THv  (-0.5403023058681398f)
#define MMv  0.8414709848078965f
#define Sv   100.0f
#define SHIFT 30.0f
#define LOG2E 1.4426950408889634f
#define SH2   (SHIFT * LOG2E)

// Scratch (no allocation allowed -> device globals)
__device__ uint32_t g_wfrag[8192];    // 32KB: normalized weight fp16, fragment order
__device__ float    g_isum[NITEMS];   // per-item NLL sums (deterministic content)
__device__ int      g_cnt;            // finished-warp counter (zero-init)
__device__ int      g_ready;          // weight-prep release counter (16 CTAs)
__device__ int      g_item = NW_TOT;  // steal counter; reset each run

// smem layout
#define OFF_A    0                    // half[128][136] rows stride 272B -> 34816 B
#define OFF_B    34816                // fragment order, 512 lane-rows x 80B -> 40960 B
#define OFF_WIN  75776                // int[8] warp finish ranks
#define OFF_FLAG 75808                // int
#define SMEM_SZ  75840

__device__ __forceinline__ float ex2(float x) {
    float r; asm("ex2.approx.f32 %0, %1;" : "=f"(r) : "f"(x)); return r;
}

__device__ __forceinline__ void hmma16816(float& c0, float& c1, float& c2, float& c3,
                                          uint32_t a0, uint32_t a1, uint32_t a2, uint32_t a3,
                                          uint32_t b0, uint32_t b1) {
    asm volatile(
        "mma.sync.aligned.m16n8k16.row.col.f32.f16.f16.f32 "
        "{%0,%1,%2,%3}, {%4,%5,%6,%7}, {%8,%9}, {%0,%1,%2,%3};"
        : "+f"(c0), "+f"(c1), "+f"(c2), "+f"(c3)
        : "r"(a0), "r"(a1), "r"(a2), "r"(a3), "r"(b0), "r"(b1));
}

// NLL from label-EXCLUDED shifted sum se = sum exp(z-30), and label cosine cs.
__device__ __forceinline__ float row_nll(float se, float cs) {
    float sn  = sqrtf(fmaxf(1.0f - cs * cs, 0.0f));
    float phi = (cs > THv) ? (cs * COSM - sn * SINM) : (cs - MMv);
    float zl  = Sv * phi;
    float se2 = se + ex2(fmaf(zl, LOG2E, -SH2));
    return (SHIFT + __logf(se2)) - zl;
}

// prefetch 8 rows (half h of item) of predict+target into registers
__device__ __forceinline__ void issue_half(const float* __restrict__ predict,
                                           const float* __restrict__ target,
                                           int item, int h, int lane,
                                           float4* Vp, float4* Vt)
{
    const size_t base = ((size_t)item * 16 + h * 8) * 32 + lane;
    const float4* p4 = (const float4*)predict;
    const float4* t4 = (const float4*)target;
    #pragma unroll
    for (int j = 0; j < 8; j++) {
        Vp[j] = __ldg(p4 + base + (size_t)j * 32);
        Vt[j] = __ldg(t4 + base + (size_t)j * 32);
    }
}

// consume 8 prefetched rows: fp16 convert + STS; ssq butterfly; ballot label
__device__ __forceinline__ void consume_half(const float4* Vp, const float4* Vt,
                                             char* sAbuf, int rowLocal, int lane, int g,
                                             float& ssOut, int& lblOut)
{
    float ssq[8];
    #pragma unroll
    for (int j = 0; j < 8; j++) {
        float4 v = Vp[j], t = Vt[j];
        __half2 h0 = __floats2half2_rn(v.x, v.y);
        __half2 h1 = __floats2half2_rn(v.z, v.w);
        unsigned long long pk;
        asm("mov.b64 %0,{%1,%2};" : "=l"(pk)
            : "r"(*(uint32_t*)&h0), "r"(*(uint32_t*)&h1));
        *reinterpret_cast<unsigned long long*>(sAbuf + (rowLocal + j) * 272 + lane * 8) = pk;
        ssq[j] = fmaf(v.x, v.x, fmaf(v.y, v.y, fmaf(v.z, v.z, v.w * v.w)));

        bool nz = (t.x > 0.5f) || (t.y > 0.5f) || (t.z > 0.5f) || (t.w > 0.5f);
        unsigned bal = __ballot_sync(0xffffffffu, nz);
        int li = (t.y > 0.5f) ? 1 : ((t.z > 0.5f) ? 2 : ((t.w > 0.5f) ? 3 : 0));
        int src = __ffs(bal) - 1;
        int lblj = 4 * src + __shfl_sync(0xffffffffu, li, src);
        if (j == g) lblOut = lblj;
    }
    #pragma unroll
    for (int o = 16; o; o >>= 1) {
        #pragma unroll
        for (int i = 0; i < 8; i++) ssq[i] += __shfl_xor_sync(0xffffffffu, ssq[i], o);
    }
    float ss = 0.f;
    #pragma unroll
    for (int i = 0; i < 8; i++) if (i == g) ss = ssq[i];
    ssOut = ss;
}

__device__ __forceinline__ void load_afrags(const char* sAbuf, int rb0, int g, int c,
                                            uint32_t* A0, uint32_t* A1,
                                            uint32_t* A2, uint32_t* A3)
{
    const char* a_lo = sAbuf + (rb0 + g) * 272 + c * 4;
    const char* a_hi = a_lo + 8 * 272;
    #pragma unroll
    for (int ks = 0; ks < 8; ks++) {
        A0[ks] = *(const uint32_t*)(a_lo + ks * 32);
        A2[ks] = *(const uint32_t*)(a_lo + ks * 32 + 16);
        A1[ks] = *(const uint32_t*)(a_hi + ks * 32);
        A3[ks] = *(const uint32_t*)(a_hi + ks * 32 + 16);
    }
}

// 8 col-tiles; B via LDS.128 fragment loads (80B lane stride, conflict-free)
__device__ __forceinline__ void mma_half(int tstart, const char* sB, int lane, int c,
    const uint32_t* A0, const uint32_t* A1, const uint32_t* A2, const uint32_t* A3,
    float sI0, float sI1, float invn0, float invn1, int lbl0, int lbl1,
    float& ac00, float& ac01, float& ac10, float& ac11, float& cs0, float& cs1)
{
    #pragma unroll
    for (int t = 0; t < 8; t++) {
        const int tt = tstart + t;
        float c0 = 0.f, c1 = 0.f, c2 = 0.f, c3 = 0.f;
        const char* bb = sB + (tt * 32 + lane) * 80;
        #pragma unroll
        for (int q = 0; q < 4; q++) {
            const uint4 bv = *(const uint4*)(bb + q * 16);
            hmma16816(c0, c1, c2, c3,
                      A0[2*q], A1[2*q], A2[2*q], A3[2*q], bv.x, bv.y);
            hmma16816(c0, c1, c2, c3,
                      A0[2*q+1], A1[2*q+1], A2[2*q+1], A3[2*q+1], bv.z, bv.w);
        }
        const int n0 = 8 * tt + 2 * c;
        float e0 = ex2(fmaf(c0, sI0, -SH2));
        float e1 = ex2(fmaf(c1, sI0, -SH2));
        float e2 = ex2(fmaf(c2, sI1, -SH2));
        float e3 = ex2(fmaf(c3, sI1, -SH2));
        if (n0     == lbl0) { cs0 = c0 * invn0; e0 = 0.f; }
        if (n0 + 1 == lbl0) { cs0 = c1 * invn0; e1 = 0.f; }
        if (n0     == lbl1) { cs1 = c2 * invn1; e2 = 0.f; }
        if (n0 + 1 == lbl1) { cs1 = c3 * invn1; e3 = 0.f; }
        ac00 += e0; ac01 += e1; ac10 += e2; ac11 += e3;
    }
}

// ---------------------------------------------------------------------------
// fused kernel: CTAs 0-15 prep weights; warps steal 16-row items dynamically
// ---------------------------------------------------------------------------
__global__ void __launch_bounds__(256, 2)
arc_main(const float* __restrict__ predict,
         const float* __restrict__ target,
         const float* __restrict__ weight,
         float* __restrict__ out)
{
    extern __shared__ char sm[];
    char*  sA   = sm + OFF_A;
    char*  sB   = sm + OFF_B;
    int*   win  = (int*)(sm + OFF_WIN);
    int*   flag = (int*)(sm + OFF_FLAG);

    const int tid  = threadIdx.x;
    const int lane = tid & 31;
    const int w    = tid >> 5;
    const int g    = lane >> 2;
    const int c    = lane & 3;
    const int rb0  = w * 16;
    const int blk  = blockIdx.x;

    if (tid == 0) *flag = 0;

    // ---- distributed weight prep: CTAs 0..15, one warp per weight row ----
    if (blk < 16) {
        const int row = blk * 8 + w;
        const int gg  = row & 7;
        const int tt  = row >> 3;
        float4 v = reinterpret_cast<const float4*>(weight)[row * 32 + lane];
        float ss = v.x * v.x + v.y * v.y + v.z * v.z + v.w * v.w;
        #pragma unroll
        for (int o = 16; o; o >>= 1) ss += __shfl_xor_sync(0xffffffffu, ss, o);
        float r = 1.0f / fmaxf(sqrtf(ss), 1e-12f);
        __half2 h0 = __floats2half2_rn(v.x * r, v.y * r);
        __half2 h1 = __floats2half2_rn(v.z * r, v.w * r);
        #pragma unroll
        for (int j = 0; j < 2; j++) {
            const int m  = 2 * lane + j;
            const int cc = m & 3, b = (m >> 2) & 1, ks = m >> 3;
            const int di = (tt * 32 + gg * 4 + cc) * 16 + 2 * ks + b;
            g_wfrag[di] = (j == 0) ? *(uint32_t*)&h0 : *(uint32_t*)&h1;
        }
        __threadfence();
        __syncthreads();
        if (tid == 0) atomicAdd(&g_ready, 1);
    }

    float4 Vp[8], Vt[8];
    uint32_t A0[8], A1[8], A2[8], A3[8];

    // ---- first item = global warp id; full prologue (no B dependence) ----
    int item = blk * 8 + w;
    float ss0, ss1; int lbl0 = 0, lbl1 = 0;
    issue_half(predict, target, item, 0, lane, Vp, Vt);
    consume_half(Vp, Vt, sA, rb0, lane, g, ss0, lbl0);
    issue_half(predict, target, item, 1, lane, Vp, Vt);
    consume_half(Vp, Vt, sA, rb0 + 8, lane, g, ss1, lbl1);
    __syncwarp();
    load_afrags(sA, rb0, g, c, A0, A1, A2, A3);
    float invn0 = rsqrtf(fmaxf(ss0, 1e-24f));
    float invn1 = rsqrtf(fmaxf(ss1, 1e-24f));

    // steal next item; prefetch its first half
    int next = (lane == 0) ? atomicAdd(&g_item, 1) : 0;
    next = __shfl_sync(0xffffffffu, next, 0);
    bool hasNext = next < NITEMS;
    if (hasNext) issue_half(predict, target, next, 0, lane, Vp, Vt);

    // ---- wait for weight prep, then stage B (spin hidden by prologue) ----
    if (tid == 0) { while (atomicAdd(&g_ready, 0) < 16) { } }
    __syncthreads();
    {
        const uint4* gw = (const uint4*)g_wfrag;
        #pragma unroll
        for (int i = 0; i < 8; i++) {
            int idx = i * 256 + tid;
            *(uint4*)(sB + (idx >> 2) * 80 + (idx & 3) * 16) = gw[idx];
        }
    }
    __syncthreads();

    float ns0 = 0.f, ns1 = 0.f; int nl0 = 0, nl1 = 0;

    while (true) {
        // steal one item ahead; latency hidden behind mma_half(0)
        int next2 = NITEMS;
        if (hasNext) {
            if (lane == 0) next2 = atomicAdd(&g_item, 1);
            next2 = __shfl_sync(0xffffffffu, next2, 0);
        }

        const float sI0 = Sv * invn0 * LOG2E, sI1 = Sv * invn1 * LOG2E;
        float ac00 = 0.f, ac01 = 0.f, ac10 = 0.f, ac11 = 0.f;
        float cs0 = -2.0f, cs1 = -2.0f;

        mma_half(0, sB, lane, c, A0, A1, A2, A3, sI0, sI1, invn0, invn1, lbl0, lbl1,
                 ac00, ac01, ac10, ac11, cs0, cs1);

        if (hasNext) {
            consume_half(Vp, Vt, sA, rb0, lane, g, ns0, nl0);
            issue_half(predict, target, next, 1, lane, Vp, Vt);
        }

        mma_half(8, sB, lane, c, A0, A1, A2, A3, sI0, sI1, invn0, invn1, lbl0, lbl1,
                 ac00, ac01, ac10, ac11, cs0, cs1);

        // ---- item epilogue: per-item NLL -> g_isum[item] (deterministic) ----
        float se0 = ac00 + ac01, se1 = ac10 + ac11;
        se0 += __shfl_xor_sync(0xffffffffu, se0, 1);
        se0 += __shfl_xor_sync(0xffffffffu, se0, 2);
        se1 += __shfl_xor_sync(0xffffffffu, se1, 1);
        se1 += __shfl_xor_sync(0xffffffffu, se1, 2);
        cs0 = fmaxf(cs0, __shfl_xor_sync(0xffffffffu, cs0, 1));
        cs0 = fmaxf(cs0, __shfl_xor_sync(0xffffffffu, cs0, 2));
        cs1 = fmaxf(cs1, __shfl_xor_sync(0xffffffffu, cs1, 1));
        cs1 = fmaxf(cs1, __shfl_xor_sync(0xffffffffu, cs1, 2));
        float nll = (c == 0) ? (row_nll(se0, cs0) + row_nll(se1, cs1)) : 0.f;
        #pragma unroll
        for (int o = 16; o >= 4; o >>= 1) nll += __shfl_xor_sync(0xffffffffu, nll, o);
        if (lane == 0) g_isum[item] = nll;

        if (!hasNext) break;

        consume_half(Vp, Vt, sA, rb0 + 8, lane, g, ns1, nl1);
        __syncwarp();
        load_afrags(sA, rb0, g, c, A0, A1, A2, A3);
        invn0 = rsqrtf(fmaxf(ns0, 1e-24f));
        invn1 = rsqrtf(fmaxf(ns1, 1e-24f));
        lbl0 = nl0; lbl1 = nl1;

        item = next; next = next2; hasNext = next2 < NITEMS;
        if (hasNext) issue_half(predict, target, next, 0, lane, Vp, Vt);
    }

    // ---- warp finish: rank via atomic; globally-last warp's CTA reduces ----
    __threadfence();
    int rank = 0;
    if (lane == 0) rank = atomicAdd(&g_cnt, 1);
    rank = __shfl_sync(0xffffffffu, rank, 0);
    if (lane == 0) win[w] = rank;
    __syncthreads();
    if (tid < 8 && win[tid] == NW_TOT - 1) *flag = 1;
    __syncthreads();

    if (*flag) {
        __threadfence();
        // deterministic fixed-order reduction of 8192 item sums
        float t = 0.f;
        #pragma unroll
        for (int k = 0; k < NITEMS / 256; k++) t += g_isum[tid + k * 256];
        float* fr = (float*)sA;
        fr[tid] = t;
        __syncthreads();
        #pragma unroll
        for (int st = 128; st; st >>= 1) {
            if (tid < st) fr[tid] += fr[tid + st];
            __syncthreads();
        }
        if (tid == 0) {
            out[0]  = fr[0] / (float)Bn;
            g_cnt   = 0;
            g_ready = 0;
            g_item  = NW_TOT;
        }
    }
}

// ---------------------------------------------------------------------------
extern "C" void kernel_launch(void* const* d_in, const int* in_sizes, int n_in,
                              void* d_out, int out_size)
{
    (void)in_sizes; (void)n_in; (void)out_size;
    const float* predict = (const float*)d_in[0];
    const float* target  = (const float*)d_in[1];
    const float* weight  = (const float*)d_in[2];

    cudaFuncSetAttribute(arc_main, cudaFuncAttributeMaxDynamicSharedMemorySize, SMEM_SZ);

    arc_main<<<NPERS, 256, SMEM_SZ>>>(predict, target, weight, (float*)d_out);
}